// round 3
// baseline (speedup 1.0000x reference)
#include <cuda_runtime.h>
#include <cuda_bf16.h>
#include <mma.h>

using namespace nvcuda;

// ---------------- problem constants ----------------
constexpr int T   = 16384;   // B*S tokens
constexpr int Dm  = 1024;    // model dim
constexpr int DFm = 4096;    // expert hidden dim
constexpr int E   = 8;       // experts
// TOP_K = 2 (hardcoded below)

// ---------------- GEMM tile config ----------------
constexpr int BM = 128, BN = 64, BK = 32;
constexpr int LDA = BK + 8;   // 40 (multiple of 8 for wmma ldm)
constexpr int LDB = BN + 8;   // 72

using FragA = wmma::fragment<wmma::matrix_a, 16, 16, 8, wmma::precision::tf32, wmma::row_major>;
using FragB = wmma::fragment<wmma::matrix_b, 16, 16, 8, wmma::precision::tf32, wmma::row_major>;
using FragC = wmma::fragment<wmma::accumulator, 16, 16, 8, float>;

// ---------------- device scratch (no allocs allowed) ----------------
__device__ int   g_counts[E];
__device__ int   g_tok[E * T];     // token index per (expert, position)
__device__ int   g_ent[E * T];     // entry id = 2*token + slot
__device__ float g_w[E * T];       // gate weight per (expert, position)
__device__ float g_H[(size_t)2 * T * DFm];   // 32768 x 4096 fp32 = 536 MB
__device__ float g_O[(size_t)2 * T * Dm];    // 32768 x 1024 fp32 = 134 MB

__device__ __forceinline__ float silu_f(float v) {
    return v / (1.0f + __expf(-v));
}

// ---------------- kernels ----------------
__global__ void zero_counts_kernel() {
    if (threadIdx.x < E) g_counts[threadIdx.x] = 0;
}

// one warp per token: 8 gate logits, top-2, softmax, list build
__global__ __launch_bounds__(256) void route_kernel(const float* __restrict__ x,
                                                    const float* __restrict__ gw) {
    int t    = (blockIdx.x * blockDim.x + threadIdx.x) >> 5;
    int lane = threadIdx.x & 31;
    if (t >= T) return;
    const float* xr = x + (size_t)t * Dm;

    float acc[E];
#pragma unroll
    for (int e = 0; e < E; e++) acc[e] = 0.0f;

    for (int c = lane; c < Dm; c += 32) {
        float xv = __ldg(xr + c);
#pragma unroll
        for (int e = 0; e < E; e++) acc[e] = fmaf(xv, __ldg(gw + e * Dm + c), acc[e]);
    }
#pragma unroll
    for (int e = 0; e < E; e++) {
#pragma unroll
        for (int o = 16; o > 0; o >>= 1) acc[e] += __shfl_xor_sync(0xFFFFFFFFu, acc[e], o);
    }

    if (lane == 0) {
        // top-2 with lowest-index tie-break (matches jax.lax.top_k)
        int bi = 0; float best = acc[0];
#pragma unroll
        for (int e = 1; e < E; e++) if (acc[e] > best) { best = acc[e]; bi = e; }
        int si = -1; float sec = -3.0e38f;
#pragma unroll
        for (int e = 0; e < E; e++) if (e != bi && acc[e] > sec) { sec = acc[e]; si = e; }

        float w1 = __expf(sec - best);     // <= 1
        float s  = 1.0f + w1;
        float w0 = 1.0f / s;
        w1       = w1 / s;

        int p0 = atomicAdd(&g_counts[bi], 1);
        g_tok[bi * T + p0] = t; g_w[bi * T + p0] = w0; g_ent[bi * T + p0] = 2 * t;
        int p1 = atomicAdd(&g_counts[si], 1);
        g_tok[si * T + p1] = t; g_w[si * T + p1] = w1; g_ent[si * T + p1] = 2 * t + 1;
    }
}

// H[entry] = silu(x[tok] @ W1[e] + b1[e]); grouped by expert, rows gathered
__global__ __launch_bounds__(256) void gemm1_kernel(const float* __restrict__ x,
                                                    const float* __restrict__ W1,
                                                    const float* __restrict__ b1) {
    const int e   = blockIdx.z;
    const int cnt = g_counts[e];
    const int m0  = blockIdx.y * BM;
    if (m0 >= cnt) return;
    const int n0  = blockIdx.x * BN;

    __shared__ __align__(16) float smem[BM * BN];  // reused: (sA|sB) mainloop, then C tile
    float* sA = smem;                  // BM*LDA = 5120 floats
    float* sB = smem + BM * LDA;       // BK*LDB = 2304 floats (total 7424 <= 8192)
    __shared__ int s_tok[BM];
    __shared__ int s_ent[BM];

    const int tid = threadIdx.x;
    for (int r = tid; r < BM; r += 256) {
        int p = m0 + r;
        int tok = 0, ent = 0;
        if (p < cnt) { tok = g_tok[e * T + p]; ent = g_ent[e * T + p]; }
        s_tok[r] = tok; s_ent[r] = ent;
    }
    __syncthreads();

    const int wid = tid >> 5;
    const int wm  = (wid >> 1) * 32;   // 0,32,64,96
    const int wn  = (wid & 1) * 32;    // 0,32

    FragC c[2][2];
#pragma unroll
    for (int i = 0; i < 2; i++)
#pragma unroll
        for (int j = 0; j < 2; j++) wmma::fill_fragment(c[i][j], 0.0f);

    const float* Be = W1 + (size_t)e * Dm * DFm;

    for (int k0 = 0; k0 < Dm; k0 += BK) {
        // A: gather 128 rows x 32 cols of x (tf32-rounded)
#pragma unroll
        for (int it = 0; it < 4; it++) {
            int idx = it * 256 + tid;            // 0..1023
            int r = idx >> 3, c4 = (idx & 7) << 2;
            float4 v = *reinterpret_cast<const float4*>(x + (size_t)s_tok[r] * Dm + k0 + c4);
            v.x = wmma::__float_to_tf32(v.x); v.y = wmma::__float_to_tf32(v.y);
            v.z = wmma::__float_to_tf32(v.z); v.w = wmma::__float_to_tf32(v.w);
            *reinterpret_cast<float4*>(sA + r * LDA + c4) = v;
        }
        // B: 32 rows x 64 cols of W1[e]
#pragma unroll
        for (int it = 0; it < 2; it++) {
            int idx = it * 256 + tid;            // 0..511
            int r = idx >> 4, c4 = (idx & 15) << 2;
            float4 v = *reinterpret_cast<const float4*>(Be + (size_t)(k0 + r) * DFm + n0 + c4);
            v.x = wmma::__float_to_tf32(v.x); v.y = wmma::__float_to_tf32(v.y);
            v.z = wmma::__float_to_tf32(v.z); v.w = wmma::__float_to_tf32(v.w);
            *reinterpret_cast<float4*>(sB + r * LDB + c4) = v;
        }
        __syncthreads();
#pragma unroll
        for (int kk = 0; kk < BK; kk += 8) {
            FragA a0, a1; FragB b0, b1;
            wmma::load_matrix_sync(a0, sA + (wm)      * LDA + kk, LDA);
            wmma::load_matrix_sync(a1, sA + (wm + 16) * LDA + kk, LDA);
            wmma::load_matrix_sync(b0, sB + kk * LDB + wn,      LDB);
            wmma::load_matrix_sync(b1, sB + kk * LDB + wn + 16, LDB);
            wmma::mma_sync(c[0][0], a0, b0, c[0][0]);
            wmma::mma_sync(c[0][1], a0, b1, c[0][1]);
            wmma::mma_sync(c[1][0], a1, b0, c[1][0]);
            wmma::mma_sync(c[1][1], a1, b1, c[1][1]);
        }
        __syncthreads();
    }

    // epilogue: frags -> smem C tile -> bias + silu -> scatter to g_H
#pragma unroll
    for (int i = 0; i < 2; i++)
#pragma unroll
        for (int j = 0; j < 2; j++)
            wmma::store_matrix_sync(smem + (wm + 16 * i) * BN + wn + 16 * j,
                                    c[i][j], BN, wmma::mem_row_major);
    __syncthreads();

    const float* b1e = b1 + e * DFm + n0;
#pragma unroll
    for (int it = 0; it < 8; it++) {
        int idx = it * 256 + tid;               // 0..2047
        int r = idx >> 4, c4 = (idx & 15) << 2;
        if (m0 + r < cnt) {
            float4 v  = *reinterpret_cast<const float4*>(smem + r * BN + c4);
            float4 bb = *reinterpret_cast<const float4*>(b1e + c4);
            v.x = silu_f(v.x + bb.x); v.y = silu_f(v.y + bb.y);
            v.z = silu_f(v.z + bb.z); v.w = silu_f(v.w + bb.w);
            *reinterpret_cast<float4*>(g_H + (size_t)s_ent[r] * DFm + n0 + c4) = v;
        }
    }
}

// O[entry] = (H[entry] @ W2[e] + b2[e]) * gate_w ; grouped by expert
__global__ __launch_bounds__(256) void gemm2_kernel(const float* __restrict__ W2,
                                                    const float* __restrict__ b2) {
    const int e   = blockIdx.z;
    const int cnt = g_counts[e];
    const int m0  = blockIdx.y * BM;
    if (m0 >= cnt) return;
    const int n0  = blockIdx.x * BN;

    __shared__ __align__(16) float smem[BM * BN];
    float* sA = smem;
    float* sB = smem + BM * LDA;
    __shared__ int   s_ent[BM];
    __shared__ float s_w[BM];

    const int tid = threadIdx.x;
    for (int r = tid; r < BM; r += 256) {
        int p = m0 + r;
        int ent = 0; float wv = 0.0f;
        if (p < cnt) { ent = g_ent[e * T + p]; wv = g_w[e * T + p]; }
        s_ent[r] = ent; s_w[r] = wv;
    }
    __syncthreads();

    const int wid = tid >> 5;
    const int wm  = (wid >> 1) * 32;
    const int wn  = (wid & 1) * 32;

    FragC c[2][2];
#pragma unroll
    for (int i = 0; i < 2; i++)
#pragma unroll
        for (int j = 0; j < 2; j++) wmma::fill_fragment(c[i][j], 0.0f);

    const float* Be = W2 + (size_t)e * DFm * Dm;

    for (int k0 = 0; k0 < DFm; k0 += BK) {
        // A: gather 128 rows x 32 cols of g_H
#pragma unroll
        for (int it = 0; it < 4; it++) {
            int idx = it * 256 + tid;
            int r = idx >> 3, c4 = (idx & 7) << 2;
            float4 v = *reinterpret_cast<const float4*>(g_H + (size_t)s_ent[r] * DFm + k0 + c4);
            v.x = wmma::__float_to_tf32(v.x); v.y = wmma::__float_to_tf32(v.y);
            v.z = wmma::__float_to_tf32(v.z); v.w = wmma::__float_to_tf32(v.w);
            *reinterpret_cast<float4*>(sA + r * LDA + c4) = v;
        }
        // B: 32 rows x 64 cols of W2[e]
#pragma unroll
        for (int it = 0; it < 2; it++) {
            int idx = it * 256 + tid;
            int r = idx >> 4, c4 = (idx & 15) << 2;
            float4 v = *reinterpret_cast<const float4*>(Be + (size_t)(k0 + r) * Dm + n0 + c4);
            v.x = wmma::__float_to_tf32(v.x); v.y = wmma::__float_to_tf32(v.y);
            v.z = wmma::__float_to_tf32(v.z); v.w = wmma::__float_to_tf32(v.w);
            *reinterpret_cast<float4*>(sB + r * LDB + c4) = v;
        }
        __syncthreads();
#pragma unroll
        for (int kk = 0; kk < BK; kk += 8) {
            FragA a0, a1; FragB b0, b1;
            wmma::load_matrix_sync(a0, sA + (wm)      * LDA + kk, LDA);
            wmma::load_matrix_sync(a1, sA + (wm + 16) * LDA + kk, LDA);
            wmma::load_matrix_sync(b0, sB + kk * LDB + wn,      LDB);
            wmma::load_matrix_sync(b1, sB + kk * LDB + wn + 16, LDB);
            wmma::mma_sync(c[0][0], a0, b0, c[0][0]);
            wmma::mma_sync(c[0][1], a0, b1, c[0][1]);
            wmma::mma_sync(c[1][0], a1, b0, c[1][0]);
            wmma::mma_sync(c[1][1], a1, b1, c[1][1]);
        }
        __syncthreads();
    }

#pragma unroll
    for (int i = 0; i < 2; i++)
#pragma unroll
        for (int j = 0; j < 2; j++)
            wmma::store_matrix_sync(smem + (wm + 16 * i) * BN + wn + 16 * j,
                                    c[i][j], BN, wmma::mem_row_major);
    __syncthreads();

    const float* b2e = b2 + e * Dm + n0;
#pragma unroll
    for (int it = 0; it < 8; it++) {
        int idx = it * 256 + tid;
        int r = idx >> 4, c4 = (idx & 15) << 2;
        if (m0 + r < cnt) {
            float  gv = s_w[r];
            float4 v  = *reinterpret_cast<const float4*>(smem + r * BN + c4);
            float4 bb = *reinterpret_cast<const float4*>(b2e + c4);
            v.x = (v.x + bb.x) * gv; v.y = (v.y + bb.y) * gv;
            v.z = (v.z + bb.z) * gv; v.w = (v.w + bb.w) * gv;
            *reinterpret_cast<float4*>(g_O + (size_t)s_ent[r] * Dm + n0 + c4) = v;
        }
    }
}

// out[t] = O[2t] + O[2t+1]
__global__ __launch_bounds__(256) void combine_kernel(float* __restrict__ out) {
    size_t i = (size_t)blockIdx.x * 256 + threadIdx.x;  // over T*Dm/4
    if (i >= (size_t)T * Dm / 4) return;
    int t = (int)(i / (Dm / 4));
    int c = (int)(i % (Dm / 4));
    const float4* O4 = reinterpret_cast<const float4*>(g_O);
    float4 a = O4[(size_t)(2 * t)     * (Dm / 4) + c];
    float4 b = O4[(size_t)(2 * t + 1) * (Dm / 4) + c];
    float4 r; r.x = a.x + b.x; r.y = a.y + b.y; r.z = a.z + b.z; r.w = a.w + b.w;
    reinterpret_cast<float4*>(out)[i] = r;
}

// ---------------- launch ----------------
extern "C" void kernel_launch(void* const* d_in, const int* in_sizes, int n_in,
                              void* d_out, int out_size) {
    const float* x  = (const float*)d_in[0];
    const float* gw = (const float*)d_in[1];
    const float* W1 = (const float*)d_in[2];
    const float* b1 = (const float*)d_in[3];
    const float* W2 = (const float*)d_in[4];
    const float* b2 = (const float*)d_in[5];
    float* out = (float*)d_out;

    zero_counts_kernel<<<1, 32>>>();
    route_kernel<<<T / 8, 256>>>(x, gw);
    gemm1_kernel<<<dim3(DFm / BN, T / BM, E), 256>>>(x, W1, b1);
    gemm2_kernel<<<dim3(Dm / BN, T / BM, E), 256>>>(W2, b2);
    combine_kernel<<<(int)(((size_t)T * Dm / 4 + 255) / 256), 256>>>(out);
}

// round 5
// speedup vs baseline: 1.6797x; 1.6797x over previous
#include <cstdint>
#include <cuda_runtime.h>
#include <cuda_bf16.h>
#include <mma.h>

using namespace nvcuda;

// ---------------- problem constants ----------------
constexpr int T   = 16384;   // B*S tokens
constexpr int Dm  = 1024;    // model dim
constexpr int DFm = 4096;    // expert hidden dim
constexpr int E   = 8;       // experts

// ---------------- GEMM tile config ----------------
constexpr int BM = 128, BN = 128, BK = 32;
constexpr int LDA = BK + 8;    // 40
constexpr int LDB = BN + 8;    // 136
constexpr int LDC = BN + 8;    // 136
constexpr int THREADS = 256;

constexpr int A_SZ     = BM * LDA;            // 5120 floats
constexpr int B_SZ     = BK * LDB;            // 4352 floats
constexpr int STAGE_SZ = A_SZ + B_SZ;         // 9472 floats
constexpr int MAIN_SZ  = 2 * STAGE_SZ;        // 18944 floats = 75776 B
constexpr int C_SZ     = BM * LDC;            // 17408 floats = 69632 B
constexpr int SMEM_BYTES = (MAIN_SZ > C_SZ ? MAIN_SZ : C_SZ) * 4;  // 75776

using FragA = wmma::fragment<wmma::matrix_a, 16, 16, 8, wmma::precision::tf32, wmma::row_major>;
using FragB = wmma::fragment<wmma::matrix_b, 16, 16, 8, wmma::precision::tf32, wmma::row_major>;
using FragC = wmma::fragment<wmma::accumulator, 16, 16, 8, float>;

// ---------------- device scratch (no allocs allowed) ----------------
__device__ int   g_counts[E];
__device__ int   g_tok[E * T];
__device__ int   g_ent[E * T];
__device__ float g_w[E * T];
__device__ float g_H[(size_t)2 * T * DFm];   // 536 MB
__device__ float g_O[(size_t)2 * T * Dm];    // 134 MB

__device__ __forceinline__ float silu_f(float v) {
    return v / (1.0f + __expf(-v));
}

#define CP_ASYNC_CG(dst_u32, src_ptr) \
    asm volatile("cp.async.cg.shared.global [%0], [%1], 16;\n" :: "r"(dst_u32), "l"(src_ptr))
#define CP_ASYNC_COMMIT() asm volatile("cp.async.commit_group;\n" ::)
#define CP_ASYNC_WAIT_ALL() asm volatile("cp.async.wait_group 0;\n" ::)

__device__ __forceinline__ unsigned smem_u32(const void* p) {
    return static_cast<unsigned>(__cvta_generic_to_shared(p));
}

// ---------------- routing ----------------
__global__ void zero_counts_kernel() {
    if (threadIdx.x < E) g_counts[threadIdx.x] = 0;
}

__global__ __launch_bounds__(256) void route_kernel(const float* __restrict__ x,
                                                    const float* __restrict__ gw) {
    int t    = (blockIdx.x * blockDim.x + threadIdx.x) >> 5;
    int lane = threadIdx.x & 31;
    if (t >= T) return;
    const float* xr = x + (size_t)t * Dm;

    float acc[E];
#pragma unroll
    for (int e = 0; e < E; e++) acc[e] = 0.0f;
    for (int c = lane; c < Dm; c += 32) {
        float xv = __ldg(xr + c);
#pragma unroll
        for (int e = 0; e < E; e++) acc[e] = fmaf(xv, __ldg(gw + e * Dm + c), acc[e]);
    }
#pragma unroll
    for (int e = 0; e < E; e++) {
#pragma unroll
        for (int o = 16; o > 0; o >>= 1) acc[e] += __shfl_xor_sync(0xFFFFFFFFu, acc[e], o);
    }

    if (lane == 0) {
        int bi = 0; float best = acc[0];
#pragma unroll
        for (int e = 1; e < E; e++) if (acc[e] > best) { best = acc[e]; bi = e; }
        int si = -1; float sec = -3.0e38f;
#pragma unroll
        for (int e = 0; e < E; e++) if (e != bi && acc[e] > sec) { sec = acc[e]; si = e; }

        float w1 = __expf(sec - best);
        float s  = 1.0f + w1;
        float w0 = 1.0f / s;
        w1       = w1 / s;

        int p0 = atomicAdd(&g_counts[bi], 1);
        g_tok[bi * T + p0] = t; g_w[bi * T + p0] = w0; g_ent[bi * T + p0] = 2 * t;
        int p1 = atomicAdd(&g_counts[si], 1);
        g_tok[si * T + p1] = t; g_w[si * T + p1] = w1; g_ent[si * T + p1] = 2 * t + 1;
    }
}

// ---------------- GEMM1: H[entry] = silu(x[tok] @ W1[e] + b1[e]) ----------------
__global__ __launch_bounds__(THREADS, 2) void gemm1_kernel(const float* __restrict__ x,
                                                           const float* __restrict__ W1,
                                                           const float* __restrict__ b1) {
    const int e   = blockIdx.z;
    const int cnt = g_counts[e];
    const int m0  = blockIdx.y * BM;
    if (m0 >= cnt) return;
    const int n0  = blockIdx.x * BN;

    extern __shared__ float smem[];
    __shared__ int s_tok[BM];
    __shared__ int s_ent[BM];

    const int tid = threadIdx.x;
    for (int r = tid; r < BM; r += THREADS) {
        int p = m0 + r;
        int tok = 0, ent = 0;
        if (p < cnt) { tok = g_tok[e * T + p]; ent = g_ent[e * T + p]; }
        s_tok[r] = tok; s_ent[r] = ent;
    }
    __syncthreads();

    const float* Be = W1 + (size_t)e * Dm * DFm;

    // stage issue: gather A rows of x, stream B rows of W1
    auto issue_stage = [&](int s, int k0) {
        float* As = smem + s * STAGE_SZ;
        float* Bs = As + A_SZ;
        unsigned sa = smem_u32(As);
        unsigned sb = smem_u32(Bs);
#pragma unroll
        for (int it = 0; it < 4; it++) {
            int c = it * THREADS + tid;        // 0..1023
            int r = c >> 3, c4 = (c & 7) << 2;
            const float* src = x + (size_t)s_tok[r] * Dm + k0 + c4;
            CP_ASYNC_CG(sa + (unsigned)(r * LDA + c4) * 4u, src);
        }
#pragma unroll
        for (int it = 0; it < 4; it++) {
            int c = it * THREADS + tid;        // 0..1023
            int r = c >> 5, c4 = (c & 31) << 2;
            const float* src = Be + (size_t)(k0 + r) * DFm + n0 + c4;
            CP_ASYNC_CG(sb + (unsigned)(r * LDB + c4) * 4u, src);
        }
        CP_ASYNC_COMMIT();
    };

    const int wid = tid >> 5;
    const int wm  = (wid & 3) * 32;     // 0,32,64,96
    const int wn  = (wid >> 2) * 64;    // 0,64

    FragC c[2][4];
#pragma unroll
    for (int i = 0; i < 2; i++)
#pragma unroll
        for (int j = 0; j < 4; j++) wmma::fill_fragment(c[i][j], 0.0f);

    issue_stage(0, 0);

    constexpr int NITER = Dm / BK;      // 32
    for (int it = 0; it < NITER; it++) {
        const int b = it & 1;
        CP_ASYNC_WAIT_ALL();
        __syncthreads();
        if (it + 1 < NITER) issue_stage(b ^ 1, (it + 1) * BK);

        const float* As = smem + b * STAGE_SZ;
        const float* Bs = As + A_SZ;
#pragma unroll
        for (int kk = 0; kk < BK; kk += 8) {
            FragA a0, a1;
            wmma::load_matrix_sync(a0, As + (wm)      * LDA + kk, LDA);
            wmma::load_matrix_sync(a1, As + (wm + 16) * LDA + kk, LDA);
#pragma unroll
            for (int q = 0; q < a0.num_elements; q++) {
                a0.x[q] = wmma::__float_to_tf32(a0.x[q]);
                a1.x[q] = wmma::__float_to_tf32(a1.x[q]);
            }
            FragB bf[4];
#pragma unroll
            for (int j = 0; j < 4; j++) {
                wmma::load_matrix_sync(bf[j], Bs + kk * LDB + wn + 16 * j, LDB);
#pragma unroll
                for (int q = 0; q < bf[j].num_elements; q++)
                    bf[j].x[q] = wmma::__float_to_tf32(bf[j].x[q]);
            }
#pragma unroll
            for (int j = 0; j < 4; j++) {
                wmma::mma_sync(c[0][j], a0, bf[j], c[0][j]);
                wmma::mma_sync(c[1][j], a1, bf[j], c[1][j]);
            }
        }
        __syncthreads();
    }

    // epilogue: frags -> smem C -> bias + silu -> scatter
#pragma unroll
    for (int i = 0; i < 2; i++)
#pragma unroll
        for (int j = 0; j < 4; j++)
            wmma::store_matrix_sync(smem + (wm + 16 * i) * LDC + wn + 16 * j,
                                    c[i][j], LDC, wmma::mem_row_major);
    __syncthreads();

    const float* b1e = b1 + e * DFm + n0;
#pragma unroll
    for (int it = 0; it < 16; it++) {
        int idx = it * THREADS + tid;          // 0..4095
        int r = idx >> 5, c4 = (idx & 31) << 2;
        if (m0 + r < cnt) {
            float4 v  = *reinterpret_cast<const float4*>(smem + r * LDC + c4);
            float4 bb = *reinterpret_cast<const float4*>(b1e + c4);
            v.x = silu_f(v.x + bb.x); v.y = silu_f(v.y + bb.y);
            v.z = silu_f(v.z + bb.z); v.w = silu_f(v.w + bb.w);
            *reinterpret_cast<float4*>(g_H + (size_t)s_ent[r] * DFm + n0 + c4) = v;
        }
    }
}

// ---------------- GEMM2: O[entry] = (H[entry] @ W2[e] + b2[e]) * gate ----------------
__global__ __launch_bounds__(THREADS, 2) void gemm2_kernel(const float* __restrict__ W2,
                                                           const float* __restrict__ b2) {
    const int e   = blockIdx.z;
    const int cnt = g_counts[e];
    const int m0  = blockIdx.y * BM;
    if (m0 >= cnt) return;
    const int n0  = blockIdx.x * BN;

    extern __shared__ float smem[];
    __shared__ int   s_ent[BM];
    __shared__ float s_w[BM];

    const int tid = threadIdx.x;
    for (int r = tid; r < BM; r += THREADS) {
        int p = m0 + r;
        int ent = 0; float wv = 0.0f;
        if (p < cnt) { ent = g_ent[e * T + p]; wv = g_w[e * T + p]; }
        s_ent[r] = ent; s_w[r] = wv;
    }
    __syncthreads();

    const float* Be = W2 + (size_t)e * DFm * Dm;

    auto issue_stage = [&](int s, int k0) {
        float* As = smem + s * STAGE_SZ;
        float* Bs = As + A_SZ;
        unsigned sa = smem_u32(As);
        unsigned sb = smem_u32(Bs);
#pragma unroll
        for (int it = 0; it < 4; it++) {
            int c = it * THREADS + tid;
            int r = c >> 3, c4 = (c & 7) << 2;
            const float* src = g_H + (size_t)s_ent[r] * DFm + k0 + c4;
            CP_ASYNC_CG(sa + (unsigned)(r * LDA + c4) * 4u, src);
        }
#pragma unroll
        for (int it = 0; it < 4; it++) {
            int c = it * THREADS + tid;
            int r = c >> 5, c4 = (c & 31) << 2;
            const float* src = Be + (size_t)(k0 + r) * Dm + n0 + c4;
            CP_ASYNC_CG(sb + (unsigned)(r * LDB + c4) * 4u, src);
        }
        CP_ASYNC_COMMIT();
    };

    const int wid = tid >> 5;
    const int wm  = (wid & 3) * 32;
    const int wn  = (wid >> 2) * 64;

    FragC c[2][4];
#pragma unroll
    for (int i = 0; i < 2; i++)
#pragma unroll
        for (int j = 0; j < 4; j++) wmma::fill_fragment(c[i][j], 0.0f);

    issue_stage(0, 0);

    constexpr int NITER = DFm / BK;     // 128
    for (int it = 0; it < NITER; it++) {
        const int b = it & 1;
        CP_ASYNC_WAIT_ALL();
        __syncthreads();
        if (it + 1 < NITER) issue_stage(b ^ 1, (it + 1) * BK);

        const float* As = smem + b * STAGE_SZ;
        const float* Bs = As + A_SZ;
#pragma unroll
        for (int kk = 0; kk < BK; kk += 8) {
            FragA a0, a1;
            wmma::load_matrix_sync(a0, As + (wm)      * LDA + kk, LDA);
            wmma::load_matrix_sync(a1, As + (wm + 16) * LDA + kk, LDA);
#pragma unroll
            for (int q = 0; q < a0.num_elements; q++) {
                a0.x[q] = wmma::__float_to_tf32(a0.x[q]);
                a1.x[q] = wmma::__float_to_tf32(a1.x[q]);
            }
            FragB bf[4];
#pragma unroll
            for (int j = 0; j < 4; j++) {
                wmma::load_matrix_sync(bf[j], Bs + kk * LDB + wn + 16 * j, LDB);
#pragma unroll
                for (int q = 0; q < bf[j].num_elements; q++)
                    bf[j].x[q] = wmma::__float_to_tf32(bf[j].x[q]);
            }
#pragma unroll
            for (int j = 0; j < 4; j++) {
                wmma::mma_sync(c[0][j], a0, bf[j], c[0][j]);
                wmma::mma_sync(c[1][j], a1, bf[j], c[1][j]);
            }
        }
        __syncthreads();
    }

#pragma unroll
    for (int i = 0; i < 2; i++)
#pragma unroll
        for (int j = 0; j < 4; j++)
            wmma::store_matrix_sync(smem + (wm + 16 * i) * LDC + wn + 16 * j,
                                    c[i][j], LDC, wmma::mem_row_major);
    __syncthreads();

    const float* b2e = b2 + e * Dm + n0;
#pragma unroll
    for (int it = 0; it < 16; it++) {
        int idx = it * THREADS + tid;
        int r = idx >> 5, c4 = (idx & 31) << 2;
        if (m0 + r < cnt) {
            float  gv = s_w[r];
            float4 v  = *reinterpret_cast<const float4*>(smem + r * LDC + c4);
            float4 bb = *reinterpret_cast<const float4*>(b2e + c4);
            v.x = (v.x + bb.x) * gv; v.y = (v.y + bb.y) * gv;
            v.z = (v.z + bb.z) * gv; v.w = (v.w + bb.w) * gv;
            *reinterpret_cast<float4*>(g_O + (size_t)s_ent[r] * Dm + n0 + c4) = v;
        }
    }
}

// ---------------- combine: out[t] = O[2t] + O[2t+1] ----------------
__global__ __launch_bounds__(256) void combine_kernel(float* __restrict__ out) {
    size_t i = (size_t)blockIdx.x * 256 + threadIdx.x;
    if (i >= (size_t)T * Dm / 4) return;
    int t = (int)(i / (Dm / 4));
    int c = (int)(i % (Dm / 4));
    const float4* O4 = reinterpret_cast<const float4*>(g_O);
    float4 a = O4[(size_t)(2 * t)     * (Dm / 4) + c];
    float4 b = O4[(size_t)(2 * t + 1) * (Dm / 4) + c];
    float4 r; r.x = a.x + b.x; r.y = a.y + b.y; r.z = a.z + b.z; r.w = a.w + b.w;
    reinterpret_cast<float4*>(out)[i] = r;
}

// ---------------- launch ----------------
extern "C" void kernel_launch(void* const* d_in, const int* in_sizes, int n_in,
                              void* d_out, int out_size) {
    const float* x  = (const float*)d_in[0];
    const float* gw = (const float*)d_in[1];
    const float* W1 = (const float*)d_in[2];
    const float* b1 = (const float*)d_in[3];
    const float* W2 = (const float*)d_in[4];
    const float* b2 = (const float*)d_in[5];
    float* out = (float*)d_out;

    static bool attr_set = false;
    if (!attr_set) {
        cudaFuncSetAttribute(gemm1_kernel, cudaFuncAttributeMaxDynamicSharedMemorySize, SMEM_BYTES);
        cudaFuncSetAttribute(gemm2_kernel, cudaFuncAttributeMaxDynamicSharedMemorySize, SMEM_BYTES);
        attr_set = true;
    }

    zero_counts_kernel<<<1, 32>>>();
    route_kernel<<<T / 8, 256>>>(x, gw);
    gemm1_kernel<<<dim3(DFm / BN, T / BM, E), THREADS, SMEM_BYTES>>>(x, W1, b1);
    gemm2_kernel<<<dim3(Dm / BN, T / BM, E), THREADS, SMEM_BYTES>>>(W2, b2);
    combine_kernel<<<(int)(((size_t)T * Dm / 4 + 255) / 256), 256>>>(out);
}